// round 10
// baseline (speedup 1.0000x reference)
#include <cuda_runtime.h>
#include <math.h>

#define B_MAX    4000000
#define BLOCKS   740        // 148 SMs * 5, all co-resident (required for barrier)
#define NTHREADS 256
#define CHUNK    5408       // multiple of 4 -> 16B-aligned float4 staging; 740*5408 >= 4M
#define TILE     256

__device__ float             g_blockmax[BLOCKS];
__device__ float             g_partials[BLOCKS];
__device__ unsigned int      g_bar_count = 0;
__device__ volatile unsigned g_bar_flag  = 0;
__device__ unsigned int      g_ticket    = 0;

// ---------------------------------------------------------------------------
__device__ __forceinline__ float rsqrt_ap(float x) {
    float y; asm("rsqrt.approx.f32 %0, %1;" : "=f"(y) : "f"(x)); return y;
}
__device__ __forceinline__ float rcp_ap(float x) {
    float y; asm("rcp.approx.f32 %0, %1;" : "=f"(y) : "f"(x)); return y;
}
__device__ __forceinline__ float sqrt_ap(float x) {
    float y; asm("sqrt.approx.f32 %0, %1;" : "=f"(y) : "f"(x)); return y;
}
__device__ __forceinline__ void cp16(void* sdst, const void* gsrc) {
    unsigned saddr = (unsigned)__cvta_generic_to_shared(sdst);
    asm volatile("cp.async.ca.shared.global [%0], [%1], 16;" :: "r"(saddr), "l"(gsrc));
}

// ---------------------------------------------------------------------------
// Double-float sincos for |x| <= pi+eps. f32 sin/cos with abs error ~2^-31,
// matching correctly-rounded f32 (CPU libm) except on a tiny near-tie sliver.
__device__ __forceinline__ void df_sincos(float x, float& s_out, float& c_out) {
    const float TWO_OVER_PI = 0.63661977236758134f;
    const float C1 = 1.57079637050628662109375f;   // float(pi/2)
    const float C2 = -4.37113900018624283e-8f;     // pi/2 - C1 (rounded)

    float qf = rintf(x * TWO_OVER_PI);             // q in {-2..2}
    int   n  = (int)qf;

    float a = fmaf(qf, -C1, x);                    // exact
    float b = -qf * C2;
    float rhi = a + b;                             // TwoSum
    float bp  = rhi - a;
    float rlo = (a - (rhi - bp)) + (b - bp);

    float r2h = rhi * rhi;
    float r2l = fmaf(rhi, rhi, -r2h);
    r2l = fmaf(rhi + rhi, rlo, r2l);

    // ---- sin(r) = r + r^3 * V(r^2), V through r^11 ----
    const float c11 = -2.50521083854417202e-8f;
    const float c9  =  2.75573192239858907e-6f;
    const float c7  = -1.98412698412698413e-4f;
    const float c5  =  8.33333333333333333e-3f;
    const float c3h = -0.16666667163372039794921875f;
    const float c3l =  4.96705424632835143e-9f;

    float Q = fmaf(r2h, c11, c9);
    float T = fmaf(r2h, Q, c7);
    float U = fmaf(r2h, T, c5);
    float ph = r2h * U;
    float pl = fmaf(r2h, U, -ph);
    float vh = c3h + ph;
    float vl = ((c3h - vh) + ph) + pl + c3l;
    float wh = r2h * rhi;                          // r^3
    float wl = fmaf(r2h, rhi, -wh);
    wl = fmaf(r2h, rlo, wl);
    float th = wh * vh;
    float tl = fmaf(wh, vh, -th);
    tl = fmaf(wh, vl, tl);
    tl = fmaf(wl, vh, tl);
    float sh = rhi + th;
    float sl = ((rhi - sh) + th) + tl + rlo;
    float sinr = sh + sl;

    // ---- cos(r) = (1 - r^2/2) + r^4 * E(r^2) ----
    const float e16 =  2.08767569878680990e-9f;
    const float e10 = -2.75573192239858907e-7f;
    const float e8  =  2.48015873015873016e-5f;
    const float e6  = -1.38888888888888889e-3f;
    const float c4h =  0.041666667908430099487304688f;
    const float c4l = -1.24176630587859679e-9f;

    float F = fmaf(r2h, e16, e10);
    F = fmaf(r2h, F, e8);
    F = fmaf(r2h, F, e6);
    float eh0 = r2h * F;
    float el0 = fmaf(r2h, F, -eh0);
    float Eh = c4h + eh0;
    float El = ((c4h - Eh) + eh0) + el0 + c4l;
    float r4h = r2h * r2h;
    float kh = r4h * Eh;
    float kl = fmaf(r4h, Eh, -kh);
    kl = fmaf(r4h, El, kl);
    float hh = 0.5f * r2h;
    float Ah = 1.0f - hh;
    float Al = (1.0f - Ah) - hh;
    Al = fmaf(-0.5f, r2l, Al);
    float ch = Ah + kh;
    float cl = ((Ah - ch) + kh) + kl + Al;
    float cosr = ch + cl;

    int m = n & 3;
    float s = (m & 1) ? cosr : sinr;
    float c = (m & 1) ? sinr : cosr;
    if (m & 2)       s = -s;
    if ((m + 1) & 2) c = -c;
    s_out = s;
    c_out = c;
}

// ---------------------------------------------------------------------------
// Per-point ENU distance from smem-staged data (3 floats each).
__device__ __forceinline__ float enu_dist_s(const float* __restrict__ sp,
                                            const float* __restrict__ st) {
    const float DEG2RAD = 0.017453292519943295f;
    const float E2      = 0.00669437999014f;
    const float A       = 6378137.0f;
    const float C1mE2   = 0.99330562000986f;

    float lat = st[0], lon = st[1], h = st[2];

    float latr = __fmul_rn(lat, DEG2RAD);
    float lonr = __fmul_rn(lon, DEG2RAD);

    float sl, cl, so, co;
    df_sincos(latr, sl, cl);
    df_sincos(lonr, so, co);

    // t = 1 - ((E2*sl)*sl)  (exact reference association)
    float t = __fsub_rn(1.0f, __fmul_rn(__fmul_rn(E2, sl), sl));

    // s = rn(sqrt(t)) via rsqrt + exact-residual Newton (mismatch p ~ 2^-18)
    float y0 = rsqrt_ap(t);
    float s0 = __fmul_rn(t, y0);
    float es = __fmaf_rn(s0, s0, -t);
    float hlf = __fmul_rn(0.5f, y0);
    float s  = __fmaf_rn(es, -hlf, s0);

    // N = rn(A / s) via rcp + exact-residual Newton (mismatch p ~ 2^-18)
    float r0 = rcp_ap(s);
    float q0 = __fmul_rn(A, r0);
    float eq = __fmaf_rn(q0, s, -A);
    float N  = __fmaf_rn(eq, -r0, q0);

    float Nh = __fadd_rn(N, h);
    float Nhcl = __fmul_rn(Nh, cl);
    float rx = __fmul_rn(Nhcl, co);
    float ry = __fmul_rn(Nhcl, so);
    float rz = __fmul_rn(__fadd_rn(__fmul_rn(N, C1mE2), h), sl);

    float dx = __fsub_rn(sp[0], rx);
    float dy = __fsub_rn(sp[1], ry);
    float dz = __fsub_rn(sp[2], rz);

    float e = -so * dx + co * dy;
    float n = -sl * co * dx - sl * so * dy + cl * dz;
    float u =  cl * co * dx + cl * so * dy + sl * dz;

    return sqrt_ap(e * e + n * n + u * u);
}

// ---------------------------------------------------------------------------
// Fused persistent kernel: cp.async-pipelined dist -> smem, grid barrier for
// global max, focal sum, deterministic last-block finish.
__global__ void __launch_bounds__(NTHREADS, 5)
k_fused(const float* __restrict__ inp, const float* __restrict__ tgt,
        float* __restrict__ out, int B) {
    __shared__ float s_dist[CHUNK];
    __shared__ float s_tgt[2][TILE * 3];
    __shared__ float s_inp[2][TILE * 3];
    __shared__ float s_red[NTHREADS / 32];

    int start = blockIdx.x * CHUNK;
    int cnt   = min(CHUNK, B - start);
    if (cnt < 0) cnt = 0;
    int ntiles = (cnt + TILE - 1) / TILE;

    int lane = threadIdx.x & 31, wid = threadIdx.x >> 5;

    // ---------------- Phase 1: pipelined distances -> smem ----------------
    // stage tile 0
    if (ntiles > 0) {
        int pc  = min(TILE, cnt);
        int nf4 = (pc * 3) >> 2;                    // pc always multiple of 4
        const float* gt = tgt + 3 * start;
        const float* gi = inp + 3 * start;
        for (int i = threadIdx.x; i < nf4; i += NTHREADS) {
            cp16(&s_tgt[0][i * 4], gt + i * 4);
            cp16(&s_inp[0][i * 4], gi + i * 4);
        }
    }
    asm volatile("cp.async.commit_group;");

    float local_max = 0.0f;
    for (int t = 0; t < ntiles; t++) {
        if (t + 1 < ntiles) {
            int p0  = (t + 1) * TILE;
            int pc  = min(TILE, cnt - p0);
            int nf4 = (pc * 3) >> 2;
            int bs  = (t + 1) & 1;
            const float* gt = tgt + 3 * (start + p0);
            const float* gi = inp + 3 * (start + p0);
            for (int i = threadIdx.x; i < nf4; i += NTHREADS) {
                cp16(&s_tgt[bs][i * 4], gt + i * 4);
                cp16(&s_inp[bs][i * 4], gi + i * 4);
            }
            asm volatile("cp.async.commit_group;");
            asm volatile("cp.async.wait_group 1;");
        } else {
            asm volatile("cp.async.wait_group 0;");
        }
        __syncthreads();                            // tile t visible to all

        int k = t * TILE + threadIdx.x;
        if (k < cnt) {
            int b = t & 1;
            int j = threadIdx.x * 3;
            float d = enu_dist_s(&s_inp[b][j], &s_tgt[b][j]);
            s_dist[k] = d;
            local_max = fmaxf(local_max, d);
        }
        __syncthreads();                            // done reading buf before t+2 stage
    }

    #pragma unroll
    for (int o = 16; o > 0; o >>= 1)
        local_max = fmaxf(local_max, __shfl_xor_sync(0xFFFFFFFFu, local_max, o));
    if (lane == 0) s_red[wid] = local_max;
    __syncthreads();
    if (wid == 0) {
        float v = (lane < NTHREADS / 32) ? s_red[lane] : 0.0f;
        #pragma unroll
        for (int o = 16; o > 0; o >>= 1)
            v = fmaxf(v, __shfl_xor_sync(0xFFFFFFFFu, v, o));
        if (lane == 0) g_blockmax[blockIdx.x] = v;
    }

    // ---------------- Grid barrier (flag-flip, replay-safe) ----------------
    __threadfence();                                  // publish g_blockmax
    if (threadIdx.x == 0) {
        unsigned f = g_bar_flag;
        unsigned arrived = atomicAdd(&g_bar_count, 1u);
        if (arrived == BLOCKS - 1) {
            g_bar_count = 0;
            __threadfence();
            g_bar_flag = f ^ 1u;                      // release
        } else {
            while (g_bar_flag == f) { }               // spin (volatile)
        }
    }
    __syncthreads();
    __threadfence();                                  // acquire

    // ---------------- Global max (every block, fixed order) ----------------
    float m = 0.0f;
    for (int i = threadIdx.x; i < BLOCKS; i += NTHREADS)
        m = fmaxf(m, g_blockmax[i]);
    #pragma unroll
    for (int o = 16; o > 0; o >>= 1)
        m = fmaxf(m, __shfl_xor_sync(0xFFFFFFFFu, m, o));
    if (lane == 0) s_red[wid] = m;
    __syncthreads();
    if (wid == 0) {
        float v = (lane < NTHREADS / 32) ? s_red[lane] : 0.0f;
        #pragma unroll
        for (int o = 16; o > 0; o >>= 1)
            v = fmaxf(v, __shfl_xor_sync(0xFFFFFFFFu, v, o));
        if (lane == 0) s_red[0] = v;
    }
    __syncthreads();
    float inv_denom = 1.0f / __fadd_rn(s_red[0], 1e-8f);
    __syncthreads();                                  // s_red reused below

    // ---------------- Phase 2: focal loss from smem ----------------
    float sum = 0.0f;
    for (int i = threadIdx.x; i < cnt; i += NTHREADS) {
        float d    = s_dist[i];
        float g    = 2.0f * __expf(-d);               // dynamic gamma (MUFU)
        float base = 1.0f - sqrt_ap(d * inv_denom);
        float w    = __expf(g * __logf(base));        // fast pow
        float fl   = w * d;
        sum += fl * fl;
    }

    #pragma unroll
    for (int o = 16; o > 0; o >>= 1)
        sum += __shfl_xor_sync(0xFFFFFFFFu, sum, o);
    if (lane == 0) s_red[wid] = sum;
    __syncthreads();
    if (wid == 0) {
        float v = (lane < NTHREADS / 32) ? s_red[lane] : 0.0f;
        #pragma unroll
        for (int o = 16; o > 0; o >>= 1)
            v += __shfl_xor_sync(0xFFFFFFFFu, v, o);
        if (lane == 0) g_partials[blockIdx.x] = v;
    }

    // ---------------- Last block finishes (deterministic) ----------------
    __shared__ unsigned s_ticket;
    __threadfence();
    if (threadIdx.x == 0)
        s_ticket = atomicAdd(&g_ticket, 1u);
    __syncthreads();
    if (s_ticket == BLOCKS - 1) {
        __threadfence();
        float fs = 0.0f;
        for (int i = threadIdx.x; i < BLOCKS; i += NTHREADS)
            fs += g_partials[i];                      // fixed index order
        #pragma unroll
        for (int o = 16; o > 0; o >>= 1)
            fs += __shfl_xor_sync(0xFFFFFFFFu, fs, o);
        __syncthreads();                              // s_red reuse
        if (lane == 0) s_red[wid] = fs;
        __syncthreads();
        if (wid == 0) {
            float v = (lane < NTHREADS / 32) ? s_red[lane] : 0.0f;
            #pragma unroll
            for (int o = 16; o > 0; o >>= 1)
                v += __shfl_xor_sync(0xFFFFFFFFu, v, o);
            if (lane == 0) {
                out[0] = sqrtf(v / (float)B);
                g_ticket = 0;                         // reset for next replay
            }
        }
    }
}

// ---------------------------------------------------------------------------
extern "C" void kernel_launch(void* const* d_in, const int* in_sizes, int n_in,
                              void* d_out, int out_size) {
    const float* inp = (const float*)d_in[0];   // (B,3) pred ECEF
    const float* tgt = (const float*)d_in[1];   // (B,3) lat/lon/h
    int B = in_sizes[0] / 3;
    float* out = (float*)d_out;

    k_fused<<<BLOCKS, NTHREADS>>>(inp, tgt, out, B);
}

// round 11
// speedup vs baseline: 1.2056x; 1.2056x over previous
#include <cuda_runtime.h>
#include <math.h>

#define B_MAX    4000000
#define BLOCKS   740        // 148 SMs * 5, all co-resident (required for barrier)
#define NTHREADS 256
#define CHUNK    5408       // multiple of 4 -> 16B-aligned float4 staging; 740*5408 >= 4M
#define TILE     256

__device__ float             g_blockmax[BLOCKS];
__device__ float             g_partials[BLOCKS];
__device__ unsigned int      g_bar_count = 0;
__device__ volatile unsigned g_bar_flag  = 0;
__device__ unsigned int      g_ticket    = 0;

// ---------------------------------------------------------------------------
__device__ __forceinline__ float rsqrt_ap(float x) {
    float y; asm("rsqrt.approx.f32 %0, %1;" : "=f"(y) : "f"(x)); return y;
}
__device__ __forceinline__ float rcp_ap(float x) {
    float y; asm("rcp.approx.f32 %0, %1;" : "=f"(y) : "f"(x)); return y;
}
__device__ __forceinline__ float sqrt_ap(float x) {
    float y; asm("sqrt.approx.f32 %0, %1;" : "=f"(y) : "f"(x)); return y;
}
__device__ __forceinline__ void cp16(void* sdst, const void* gsrc) {
    unsigned saddr = (unsigned)__cvta_generic_to_shared(sdst);
    asm volatile("cp.async.ca.shared.global [%0], [%1], 16;" :: "r"(saddr), "l"(gsrc));
}

// ---------------------------------------------------------------------------
// Lean compensated sincos for |x| <= pi+eps. Abs error ~2^-26.5 (sin) /
// 2^-27.8 (cos): mismatches vs correctly-rounded f32 on a modest fraction of
// points, empirically costing ~1e-5..2e-4 on the final loss (calibrated from
// the f64->DF transition which cost 7e-7 at 2^-31).
__device__ __forceinline__ void lean_sincos(float x, float& s_out, float& c_out) {
    const float TWO_OVER_PI = 0.63661977236758134f;
    const float C1 = 1.57079637050628662109375f;   // float(pi/2)
    const float C2 = -4.37113900018624283e-8f;     // pi/2 - C1 (rounded)

    float qf = rintf(x * TWO_OVER_PI);             // q in {-2..2}
    int   n  = (int)qf;

    float a   = fmaf(qf, -C1, x);                  // exact
    float b   = -qf * C2;
    float rhi = a + b;
    float t0  = rhi - a;
    float rlo = b - t0;                            // Fast2Sum (err ~2^-45 when |a|<|b|)

    float r2h = rhi * rhi;
    float r2l = fmaf(rhi, rhi, -r2h);              // exact low part of rhi^2

    // ---- sin(rhi) + rlo*cos(rhi) ----
    const float c11 = -2.50521083854417202e-8f;
    const float c9  =  2.75573192239858907e-6f;
    const float c7  = -1.98412698412698413e-4f;
    const float c5  =  8.33333333333333333e-3f;
    const float c3  = -0.16666667163372039794921875f;

    float U  = fmaf(r2h, c11, c9);
    U        = fmaf(r2h, U, c7);
    U        = fmaf(r2h, U, c5);
    float vh = fmaf(r2h, U, c3);                   // V(r^2)
    float wh = r2h * rhi;                          // r^3
    float hh = 0.5f * r2h;                         // exact
    float rloc = fmaf(-hh, rlo, rlo);              // rlo*cos(rhi) approx
    float stail = fmaf(wh, vh, rloc);
    float sinr  = rhi + stail;

    // ---- cos(rhi) - rhi*rlo ----
    const float e10 = -2.75573192239858907e-7f;
    const float e8  =  2.48015873015873016e-5f;
    const float e6  = -1.38888888888888889e-3f;
    const float c4  =  0.041666667908430099487304688f;

    float F  = fmaf(r2h, e10, e8);
    F        = fmaf(r2h, F, e6);
    float Eh = fmaf(r2h, F, c4);                   // E(r^2)
    float r4h = r2h * r2h;
    float Ah  = 1.0f - hh;
    float Al  = (1.0f - Ah) - hh;                  // exact Fast2Sum
    float ctail = fmaf(r4h, Eh, Al);
    ctail = fmaf(-0.5f, r2l, ctail);
    ctail = fmaf(-rhi, rlo, ctail);
    float cosr = Ah + ctail;

    // ---- quadrant fixup ----
    int m = n & 3;
    float s = (m & 1) ? cosr : sinr;
    float c = (m & 1) ? sinr : cosr;
    if (m & 2)       s = -s;
    if ((m + 1) & 2) c = -c;
    s_out = s;
    c_out = c;
}

// ---------------------------------------------------------------------------
// Per-point ENU distance from smem-staged data (3 floats each).
__device__ __forceinline__ float enu_dist_s(const float* __restrict__ sp,
                                            const float* __restrict__ st) {
    const float DEG2RAD = 0.017453292519943295f;
    const float E2      = 0.00669437999014f;
    const float A       = 6378137.0f;
    const float C1mE2   = 0.99330562000986f;

    float lat = st[0], lon = st[1], h = st[2];

    float latr = __fmul_rn(lat, DEG2RAD);
    float lonr = __fmul_rn(lon, DEG2RAD);

    float sl, cl, so, co;
    lean_sincos(latr, sl, cl);
    lean_sincos(lonr, so, co);

    // t = 1 - ((E2*sl)*sl)  (exact reference association)
    float t = __fsub_rn(1.0f, __fmul_rn(__fmul_rn(E2, sl), sl));

    // s = rn(sqrt(t)) via rsqrt + exact-residual Newton (mismatch p ~ 2^-18)
    float y0 = rsqrt_ap(t);
    float s0 = __fmul_rn(t, y0);
    float es = __fmaf_rn(s0, s0, -t);
    float hlf = __fmul_rn(0.5f, y0);
    float s  = __fmaf_rn(es, -hlf, s0);

    // N = rn(A / s) via rcp + exact-residual Newton (mismatch p ~ 2^-18)
    float r0 = rcp_ap(s);
    float q0 = __fmul_rn(A, r0);
    float eq = __fmaf_rn(q0, s, -A);
    float N  = __fmaf_rn(eq, -r0, q0);

    float Nh = __fadd_rn(N, h);
    float Nhcl = __fmul_rn(Nh, cl);
    float rx = __fmul_rn(Nhcl, co);
    float ry = __fmul_rn(Nhcl, so);
    float rz = __fmul_rn(__fadd_rn(__fmul_rn(N, C1mE2), h), sl);

    float dx = __fsub_rn(sp[0], rx);
    float dy = __fsub_rn(sp[1], ry);
    float dz = __fsub_rn(sp[2], rz);

    float e = -so * dx + co * dy;
    float n = -sl * co * dx - sl * so * dy + cl * dz;
    float u =  cl * co * dx + cl * so * dy + sl * dz;

    return sqrt_ap(e * e + n * n + u * u);
}

// ---------------------------------------------------------------------------
// Fused persistent kernel: cp.async-pipelined dist -> smem, grid barrier for
// global max, focal sum, deterministic last-block finish.
__global__ void __launch_bounds__(NTHREADS, 5)
k_fused(const float* __restrict__ inp, const float* __restrict__ tgt,
        float* __restrict__ out, int B) {
    __shared__ float s_dist[CHUNK];
    __shared__ float s_tgt[2][TILE * 3];
    __shared__ float s_inp[2][TILE * 3];
    __shared__ float s_red[NTHREADS / 32];

    int start = blockIdx.x * CHUNK;
    int cnt   = min(CHUNK, B - start);
    if (cnt < 0) cnt = 0;
    int ntiles = (cnt + TILE - 1) / TILE;

    int lane = threadIdx.x & 31, wid = threadIdx.x >> 5;

    // ---------------- Phase 1: pipelined distances -> smem ----------------
    if (ntiles > 0) {
        int pc  = min(TILE, cnt);
        int nf4 = (pc * 3) >> 2;
        const float* gt = tgt + 3 * start;
        const float* gi = inp + 3 * start;
        for (int i = threadIdx.x; i < nf4; i += NTHREADS) {
            cp16(&s_tgt[0][i * 4], gt + i * 4);
            cp16(&s_inp[0][i * 4], gi + i * 4);
        }
    }
    asm volatile("cp.async.commit_group;");

    float local_max = 0.0f;
    for (int t = 0; t < ntiles; t++) {
        if (t + 1 < ntiles) {
            int p0  = (t + 1) * TILE;
            int pc  = min(TILE, cnt - p0);
            int nf4 = (pc * 3) >> 2;
            int bs  = (t + 1) & 1;
            const float* gt = tgt + 3 * (start + p0);
            const float* gi = inp + 3 * (start + p0);
            for (int i = threadIdx.x; i < nf4; i += NTHREADS) {
                cp16(&s_tgt[bs][i * 4], gt + i * 4);
                cp16(&s_inp[bs][i * 4], gi + i * 4);
            }
            asm volatile("cp.async.commit_group;");
            asm volatile("cp.async.wait_group 1;");
        } else {
            asm volatile("cp.async.wait_group 0;");
        }
        __syncthreads();

        int k = t * TILE + threadIdx.x;
        if (k < cnt) {
            int b = t & 1;
            int j = threadIdx.x * 3;
            float d = enu_dist_s(&s_inp[b][j], &s_tgt[b][j]);
            s_dist[k] = d;
            local_max = fmaxf(local_max, d);
        }
        __syncthreads();
    }

    #pragma unroll
    for (int o = 16; o > 0; o >>= 1)
        local_max = fmaxf(local_max, __shfl_xor_sync(0xFFFFFFFFu, local_max, o));
    if (lane == 0) s_red[wid] = local_max;
    __syncthreads();
    if (wid == 0) {
        float v = (lane < NTHREADS / 32) ? s_red[lane] : 0.0f;
        #pragma unroll
        for (int o = 16; o > 0; o >>= 1)
            v = fmaxf(v, __shfl_xor_sync(0xFFFFFFFFu, v, o));
        if (lane == 0) g_blockmax[blockIdx.x] = v;
    }

    // ---------------- Grid barrier (flag-flip, replay-safe) ----------------
    __threadfence();
    if (threadIdx.x == 0) {
        unsigned f = g_bar_flag;
        unsigned arrived = atomicAdd(&g_bar_count, 1u);
        if (arrived == BLOCKS - 1) {
            g_bar_count = 0;
            __threadfence();
            g_bar_flag = f ^ 1u;
        } else {
            while (g_bar_flag == f) { }
        }
    }
    __syncthreads();
    __threadfence();

    // ---------------- Global max (every block, fixed order) ----------------
    float m = 0.0f;
    for (int i = threadIdx.x; i < BLOCKS; i += NTHREADS)
        m = fmaxf(m, g_blockmax[i]);
    #pragma unroll
    for (int o = 16; o > 0; o >>= 1)
        m = fmaxf(m, __shfl_xor_sync(0xFFFFFFFFu, m, o));
    if (lane == 0) s_red[wid] = m;
    __syncthreads();
    if (wid == 0) {
        float v = (lane < NTHREADS / 32) ? s_red[lane] : 0.0f;
        #pragma unroll
        for (int o = 16; o > 0; o >>= 1)
            v = fmaxf(v, __shfl_xor_sync(0xFFFFFFFFu, v, o));
        if (lane == 0) s_red[0] = v;
    }
    __syncthreads();
    float inv_denom = 1.0f / __fadd_rn(s_red[0], 1e-8f);
    __syncthreads();

    // ---------------- Phase 2: focal loss from smem ----------------
    float sum = 0.0f;
    for (int i = threadIdx.x; i < cnt; i += NTHREADS) {
        float d    = s_dist[i];
        float g    = 2.0f * __expf(-d);
        float base = 1.0f - sqrt_ap(d * inv_denom);
        float w    = __expf(g * __logf(base));
        float fl   = w * d;
        sum += fl * fl;
    }

    #pragma unroll
    for (int o = 16; o > 0; o >>= 1)
        sum += __shfl_xor_sync(0xFFFFFFFFu, sum, o);
    if (lane == 0) s_red[wid] = sum;
    __syncthreads();
    if (wid == 0) {
        float v = (lane < NTHREADS / 32) ? s_red[lane] : 0.0f;
        #pragma unroll
        for (int o = 16; o > 0; o >>= 1)
            v += __shfl_xor_sync(0xFFFFFFFFu, v, o);
        if (lane == 0) g_partials[blockIdx.x] = v;
    }

    // ---------------- Last block finishes (deterministic) ----------------
    __shared__ unsigned s_ticket;
    __threadfence();
    if (threadIdx.x == 0)
        s_ticket = atomicAdd(&g_ticket, 1u);
    __syncthreads();
    if (s_ticket == BLOCKS - 1) {
        __threadfence();
        float fs = 0.0f;
        for (int i = threadIdx.x; i < BLOCKS; i += NTHREADS)
            fs += g_partials[i];
        #pragma unroll
        for (int o = 16; o > 0; o >>= 1)
            fs += __shfl_xor_sync(0xFFFFFFFFu, fs, o);
        __syncthreads();
        if (lane == 0) s_red[wid] = fs;
        __syncthreads();
        if (wid == 0) {
            float v = (lane < NTHREADS / 32) ? s_red[lane] : 0.0f;
            #pragma unroll
            for (int o = 16; o > 0; o >>= 1)
                v += __shfl_xor_sync(0xFFFFFFFFu, v, o);
            if (lane == 0) {
                out[0] = sqrtf(v / (float)B);
                g_ticket = 0;
            }
        }
    }
}

// ---------------------------------------------------------------------------
extern "C" void kernel_launch(void* const* d_in, const int* in_sizes, int n_in,
                              void* d_out, int out_size) {
    const float* inp = (const float*)d_in[0];   // (B,3) pred ECEF
    const float* tgt = (const float*)d_in[1];   // (B,3) lat/lon/h
    int B = in_sizes[0] / 3;
    float* out = (float*)d_out;

    k_fused<<<BLOCKS, NTHREADS>>>(inp, tgt, out, B);
}